// round 16
// baseline (speedup 1.0000x reference)
#include <cuda_runtime.h>
#include <cuda_bf16.h>
#include <math_constants.h>

#define B        256
#define N_IN     4096
#define N_MID    4096
#define N_OUT    1024
#define AM_PAIRS 6144            // blocks; each handles rows bid and bid+6144

// Scratch (device globals — no allocation allowed)
__device__ __align__(16) int g_dest1[N_IN];
__device__ __align__(16) int g_dest2[N_MID];
__device__ __align__(16) int g_dest3[N_MID];   // W3 has 4096 rows
__device__ __align__(16) int g_route[N_IN];    // dest3[dest2[dest1[s]]]

// Map a virtual row id [0,12288) to (W, dest, row, wide)
__device__ __forceinline__ void resolve(
    int vid, const float* W1, const float* W2, const float* W3,
    const float*& W, int*& dest, int& row, bool& wide)
{
    if (vid < N_IN)            { W = W1; dest = g_dest1; row = vid;           wide = true;  }
    else if (vid < 2 * N_IN)   { W = W2; dest = g_dest2; row = vid - N_IN;    wide = true;  }
    else                       { W = W3; dest = g_dest3; row = vid - 2*N_IN;  wide = false; }
}

__device__ __forceinline__ float max16(const float4& a, const float4& b,
                                       const float4& c, const float4& d)
{
    float m0 = fmaxf(fmaxf(a.x, a.y), fmaxf(a.z, a.w));
    float m1 = fmaxf(fmaxf(b.x, b.y), fmaxf(b.z, b.w));
    float m2 = fmaxf(fmaxf(c.x, c.y), fmaxf(c.z, c.w));
    float m3 = fmaxf(fmaxf(d.x, d.y), fmaxf(d.z, d.w));
    return fmaxf(fmaxf(m0, m1), fmaxf(m2, m3));
}

__device__ __forceinline__ void recover4(const float4& v, float bm, int base, int& cand)
{
    if (v.x == bm) cand = min(cand, base    );
    if (v.y == bm) cand = min(cand, base + 1);
    if (v.z == bm) cand = min(cand, base + 2);
    if (v.w == bm) cand = min(cand, base + 3);
}

// ---------------------------------------------------------------------------
// Argmax, two rows per block. Row0 (vid=bid) is always a wide row; row1
// (vid=bid+6144) is wide for bid<2048, else a narrow W3 row. The two rows
// share the block's two __syncthreads and smem round trips, halving the
// reduction overhead per row and doubling per-thread MLP.
// Ties -> smallest index (matching jnp.argmax).
// ---------------------------------------------------------------------------
__global__ void __launch_bounds__(256, 4) argmax_all_kernel(
    const float* __restrict__ W1, const float* __restrict__ W2,
    const float* __restrict__ W3)
{
    const int bid  = blockIdx.x;
    const int tid  = threadIdx.x;
    const int lane = tid & 31;
    const int wid  = tid >> 5;

    const float *Wa, *Wb;
    int *desta, *destb;
    int rowa, rowb;
    bool widea, wideb;
    resolve(bid,            W1, W2, W3, Wa, desta, rowa, widea);
    resolve(bid + AM_PAIRS, W1, W2, W3, Wb, destb, rowb, wideb);

    // ---- Front-batched loads for both rows ----
    float4 a0, b0, c0, d0;          // row0: always wide
    {
        const float4* __restrict__ r4 =
            reinterpret_cast<const float4*>(Wa + (size_t)rowa * N_MID);
        a0 = r4[tid];
        b0 = r4[tid + 256];
        c0 = r4[tid + 512];
        d0 = r4[tid + 768];
    }
    float4 a1, b1, c1, d1;          // row1: wide or narrow
    if (wideb) {
        const float4* __restrict__ r4 =
            reinterpret_cast<const float4*>(Wb + (size_t)rowb * N_MID);
        a1 = r4[tid];
        b1 = r4[tid + 256];
        c1 = r4[tid + 512];
        d1 = r4[tid + 768];
    } else {
        const float4* __restrict__ r4 =
            reinterpret_cast<const float4*>(Wb + (size_t)rowb * N_OUT);
        a1 = r4[tid];
    }

    // ---- Thread-local maxes ----
    float m0 = max16(a0, b0, c0, d0);
    float m1 = wideb ? max16(a1, b1, c1, d1)
                     : fmaxf(fmaxf(a1.x, a1.y), fmaxf(a1.z, a1.w));

    // ---- Warp maxes (independent -> interleaved shuffles, good ILP) ----
    #pragma unroll
    for (int off = 16; off > 0; off >>= 1) {
        m0 = fmaxf(m0, __shfl_xor_sync(0xFFFFFFFFu, m0, off));
        m1 = fmaxf(m1, __shfl_xor_sync(0xFFFFFFFFu, m1, off));
    }

    __shared__ float s_w0[8], s_w1[8];
    __shared__ int   s_i0[8], s_i1[8];
    if (lane == 0) { s_w0[wid] = m0; s_w1[wid] = m1; }
    __syncthreads();
    float bm0 = s_w0[0], bm1 = s_w1[0];
    #pragma unroll
    for (int w = 1; w < 8; w++) {
        bm0 = fmaxf(bm0, s_w0[w]);
        bm1 = fmaxf(bm1, s_w1[w]);
    }

    // ---- Index recovery for both rows ----
    int c0i = 0x7FFFFFFF, c1i = 0x7FFFFFFF;
    {
        int g0 = tid*4, g1 = (tid+256)*4, g2 = (tid+512)*4, g3 = (tid+768)*4;
        recover4(a0, bm0, g0, c0i);
        recover4(b0, bm0, g1, c0i);
        recover4(c0, bm0, g2, c0i);
        recover4(d0, bm0, g3, c0i);
        if (wideb) {
            recover4(a1, bm1, g0, c1i);
            recover4(b1, bm1, g1, c1i);
            recover4(c1, bm1, g2, c1i);
            recover4(d1, bm1, g3, c1i);
        } else {
            recover4(a1, bm1, tid*4, c1i);
        }
    }

    #pragma unroll
    for (int off = 16; off > 0; off >>= 1) {
        c0i = min(c0i, __shfl_xor_sync(0xFFFFFFFFu, c0i, off));
        c1i = min(c1i, __shfl_xor_sync(0xFFFFFFFFu, c1i, off));
    }
    if (lane == 0) { s_i0[wid] = c0i; s_i1[wid] = c1i; }
    __syncthreads();
    if (tid == 0) {
        int i0 = s_i0[0], i1 = s_i1[0];
        #pragma unroll
        for (int w = 1; w < 8; w++) {
            i0 = min(i0, s_i0[w]);
            i1 = min(i1, s_i1[w]);
        }
        desta[rowa] = i0;
        destb[rowb] = i1;
    }
}

// ---------------------------------------------------------------------------
// Compose route once (PDL secondary of argmax).
// ---------------------------------------------------------------------------
__global__ void __launch_bounds__(256) compose_kernel()
{
#if __CUDA_ARCH__ >= 900
    cudaGridDependencySynchronize();
#endif
    int s = blockIdx.x * 256 + threadIdx.x;
    g_route[s] = g_dest3[g_dest2[g_dest1[s]]];
}

// ---------------------------------------------------------------------------
// Scatter (PDL secondary of compose): preamble overlaps upstream drain.
// ---------------------------------------------------------------------------
__global__ void __launch_bounds__(1024) scatter_kernel(
    const int* __restrict__ x, float* __restrict__ out)
{
    __shared__ int acc[N_OUT];
    const int b   = blockIdx.x;
    const int tid = threadIdx.x;

    const int4* __restrict__ xb4 =
        reinterpret_cast<const int4*>(x + (size_t)b * N_IN);
    int4 v = xb4[tid];               // DRAM stream, coalesced
    if (tid < N_OUT) acc[tid] = 0;
    __syncthreads();

#if __CUDA_ARCH__ >= 900
    cudaGridDependencySynchronize();
#endif
    int4 r = reinterpret_cast<const int4*>(g_route)[tid];  // L2-hot
    atomicAdd(&acc[r.x], v.x);
    atomicAdd(&acc[r.y], v.y);
    atomicAdd(&acc[r.z], v.z);
    atomicAdd(&acc[r.w], v.w);
    __syncthreads();

    if (tid < N_OUT)
        out[(size_t)b * N_OUT + tid] = (float)acc[tid];
}

// ---------------------------------------------------------------------------
static void launch_pdl(const void* fn, dim3 grid, dim3 block, void** args)
{
    cudaLaunchConfig_t cfg = {};
    cfg.gridDim  = grid;
    cfg.blockDim = block;
    cfg.dynamicSmemBytes = 0;
    cfg.stream = 0;
    cudaLaunchAttribute attr[1];
    attr[0].id = cudaLaunchAttributeProgrammaticStreamSerialization;
    attr[0].val.programmaticStreamSerializationAllowed = 1;
    cfg.attrs = attr;
    cfg.numAttrs = 1;
    cudaLaunchKernelExC(&cfg, fn, args);
}

extern "C" void kernel_launch(void* const* d_in, const int* in_sizes, int n_in,
                              void* d_out, int out_size)
{
    const int*   x  = (const int*)d_in[0];
    const float* W1 = (const float*)d_in[1];
    const float* W2 = (const float*)d_in[2];
    const float* W3 = (const float*)d_in[3];
    float* out = (float*)d_out;

    argmax_all_kernel<<<AM_PAIRS, 256>>>(W1, W2, W3);

    void* compose_args[] = {};
    launch_pdl((const void*)compose_kernel, dim3(N_IN / 256), dim3(256),
               compose_args);

    void* scatter_args[] = {(void*)&x, (void*)&out};
    launch_pdl((const void*)scatter_kernel, dim3(B), dim3(1024),
               scatter_args);
}